// round 2
// baseline (speedup 1.0000x reference)
#include <cuda_runtime.h>
#include <cstdint>
#include <cstddef>

#define NU 100000
#define NI 200000
#define BB 3
#define EE 1000000
#define DD 64

// Scratch (device globals: allocation-free per harness rules)
__device__ float g_uscr[(size_t)BB * NU * DD];   // 76.8 MB  pre-activations (user side)
__device__ float g_iscr[(size_t)BB * NI * DD];   // 153.6 MB pre-activations (item side)
__device__ float g_zi[(size_t)NI * DD];          // 51.2 MB  item_emb @ u_w
__device__ float g_zu[(size_t)NU * DD];          // 25.6 MB  user_emb @ i_w

// ---------------------------------------------------------------------------
// Pre-GEMM: Z = X @ W   (X: [N,64], W: [64,64] row-major (k, col))
// 32 rows per block, 256 threads. Thread (g=t>>5, c=t&31):
// rows {g+8i, i<4}, cols {c, c+32} -> 8 fp32 accumulators.
// ---------------------------------------------------------------------------
#define F4_GET(v, kk) ((kk) == 0 ? (v).x : ((kk) == 1 ? (v).y : ((kk) == 2 ? (v).z : (v).w)))

__global__ void __launch_bounds__(256) gemm64(
    const float* __restrict__ X,
    const float* __restrict__ W,
    float*       __restrict__ Z,
    int N)
{
    __shared__ float4 sX[32 * 16];   // 8 KB
    __shared__ float  sW[64 * 64];   // 16 KB

    int t  = threadIdx.x;
    int n0 = blockIdx.x * 32;

    const float4* X4 = reinterpret_cast<const float4*>(X);
    #pragma unroll
    for (int i = 0; i < 2; i++) {
        int u = t + i * 256;                 // 0..511
        sX[u] = X4[((size_t)n0 + (u >> 4)) * 16 + (u & 15)];
    }
    const float4* W4  = reinterpret_cast<const float4*>(W);
    float4*       sW4 = reinterpret_cast<float4*>(sW);
    #pragma unroll
    for (int i = 0; i < 4; i++) sW4[t + i * 256] = W4[t + i * 256];
    __syncthreads();

    int c = t & 31;
    int g = t >> 5;

    float acc[4][2];
    #pragma unroll
    for (int i = 0; i < 4; i++) { acc[i][0] = 0.0f; acc[i][1] = 0.0f; }

    #pragma unroll
    for (int k4 = 0; k4 < 16; k4++) {
        float4 xv[4];
        #pragma unroll
        for (int i = 0; i < 4; i++)
            xv[i] = sX[(g + 8 * i) * 16 + k4];          // warp broadcast

        #pragma unroll
        for (int kk = 0; kk < 4; kk++) {
            int k = k4 * 4 + kk;
            float w0 = sW[k * 64 + c];
            float w1 = sW[k * 64 + c + 32];
            #pragma unroll
            for (int i = 0; i < 4; i++) {
                float xk = F4_GET(xv[i], kk);
                acc[i][0] = fmaf(xk, w0, acc[i][0]);
                acc[i][1] = fmaf(xk, w1, acc[i][1]);
            }
        }
    }

    #pragma unroll
    for (int i = 0; i < 4; i++) {
        size_t row = (size_t)n0 + g + 8 * i;
        Z[row * 64 + c]      = acc[i][0];
        Z[row * 64 + c + 32] = acc[i][1];
    }
}

// ---------------------------------------------------------------------------
// Scatter: COO spmm  out[row] += val * Z[col]   (red.global.add.v4.f32)
// One warp handles 32 edges: coalesced metadata load, shfl-distribute,
// 16 lanes per edge, one v4 red per lane.
// ---------------------------------------------------------------------------
__global__ void __launch_bounds__(256) scatter_kernel(
    const float* __restrict__ vals,
    const int*   __restrict__ rows,
    const int*   __restrict__ cols,
    const float* __restrict__ dense,
    float*       __restrict__ out,
    int nE)
{
    int warp = (blockIdx.x * blockDim.x + threadIdx.x) >> 5;
    int lane = threadIdx.x & 31;
    int e = warp * 32 + lane;

    float v = 0.0f; int r = 0, c = 0;
    if (e < nE) { v = vals[e]; r = rows[e]; c = cols[e]; }   // tail: v=0 -> adds 0

    int half = lane >> 4;
    int l4   = lane & 15;

    #pragma unroll
    for (int i = 0; i < 16; i++) {
        int src = 2 * i + half;
        float vv = __shfl_sync(0xffffffffu, v, src);
        int   rr = __shfl_sync(0xffffffffu, r, src);
        int   cc = __shfl_sync(0xffffffffu, c, src);

        const float4* dp = reinterpret_cast<const float4*>(dense + (size_t)cc * DD) + l4;
        float4 d = __ldg(dp);
        float4 p;
        p.x = vv * d.x; p.y = vv * d.y; p.z = vv * d.z; p.w = vv * d.w;

        float* op = out + (size_t)rr * DD + (size_t)l4 * 4;
        asm volatile("red.global.add.v4.f32 [%0], {%1,%2,%3,%4};"
                     :: "l"(op), "f"(p.x), "f"(p.y), "f"(p.z), "f"(p.w)
                     : "memory");
    }
}

// ---------------------------------------------------------------------------
// Epilogue: per-behavior sigmoid + sigmoid of behavior-mean (pure elementwise)
// scr: [3, N, 64] pre-activations -> out_per: [3, N, 64], out_mean: [N, 64]
// ---------------------------------------------------------------------------
__device__ __forceinline__ float sigmoidf_(float x) {
    return 1.0f / (1.0f + __expf(-x));
}

__global__ void __launch_bounds__(256) epilogue(
    const float* __restrict__ scr,
    float*       __restrict__ out_per,
    float*       __restrict__ out_mean,
    int N)
{
    size_t idx = (size_t)blockIdx.x * blockDim.x + threadIdx.x;   // over N*16 float4s
    size_t stride = (size_t)N * 16;

    const float4* s4 = reinterpret_cast<const float4*>(scr);
    float4* p4 = reinterpret_cast<float4*>(out_per);
    float4* m4 = reinterpret_cast<float4*>(out_mean);

    float4 s0 = s4[idx];
    float4 s1 = s4[idx + stride];
    float4 s2 = s4[idx + 2 * stride];

    float4 o;
    o.x = sigmoidf_(s0.x); o.y = sigmoidf_(s0.y); o.z = sigmoidf_(s0.z); o.w = sigmoidf_(s0.w);
    p4[idx] = o;
    o.x = sigmoidf_(s1.x); o.y = sigmoidf_(s1.y); o.z = sigmoidf_(s1.z); o.w = sigmoidf_(s1.w);
    p4[idx + stride] = o;
    o.x = sigmoidf_(s2.x); o.y = sigmoidf_(s2.y); o.z = sigmoidf_(s2.z); o.w = sigmoidf_(s2.w);
    p4[idx + 2 * stride] = o;

    const float third = 1.0f / 3.0f;
    float4 m;
    m.x = sigmoidf_((s0.x + s1.x + s2.x) * third);
    m.y = sigmoidf_((s0.y + s1.y + s2.y) * third);
    m.z = sigmoidf_((s0.z + s1.z + s2.z) * third);
    m.w = sigmoidf_((s0.w + s1.w + s2.w) * third);
    m4[idx] = m;
}

// ---------------------------------------------------------------------------
// Launch
// ---------------------------------------------------------------------------
extern "C" void kernel_launch(void* const* d_in, const int* in_sizes, int n_in,
                              void* d_out, int out_size)
{
    const float* user_emb = (const float*)d_in[0];
    const float* item_emb = (const float*)d_in[1];
    const float* u2i_vals = (const float*)d_in[2];
    const int*   u2i_rows = (const int*)  d_in[3];
    const int*   u2i_cols = (const int*)  d_in[4];
    const float* i2u_vals = (const float*)d_in[5];
    const int*   i2u_rows = (const int*)  d_in[6];
    const int*   i2u_cols = (const int*)  d_in[7];
    const float* u_w      = (const float*)d_in[8];
    const float* i_w      = (const float*)d_in[9];

    float* out     = (float*)d_out;
    float* out_ue  = out;                                                 // [NU,64]
    float* out_ie  = out + (size_t)NU * DD;                               // [NI,64]
    float* out_ues = out + (size_t)(NU + NI) * DD;                        // [3,NU,64]
    float* out_ies = out + (size_t)(NU + NI) * DD + (size_t)BB * NU * DD; // [3,NI,64]

    void* p;
    cudaGetSymbolAddress(&p, g_uscr); float* uscr = (float*)p;
    cudaGetSymbolAddress(&p, g_iscr); float* iscr = (float*)p;
    cudaGetSymbolAddress(&p, g_zi);   float* zi   = (float*)p;
    cudaGetSymbolAddress(&p, g_zu);   float* zu   = (float*)p;

    cudaMemsetAsync(uscr, 0, sizeof(g_uscr), 0);
    cudaMemsetAsync(iscr, 0, sizeof(g_iscr), 0);

    // Pre-transform: Z_item = item_emb @ u_w ; Z_user = user_emb @ i_w
    gemm64<<<NI / 32, 256>>>(item_emb, u_w, zi, NI);
    gemm64<<<NU / 32, 256>>>(user_emb, i_w, zu, NU);

    // Scatter transformed rows (scratch accumulates pre-activations)
    int sblocks = (EE + 255) / 256;
    for (int b = 0; b < BB; b++) {
        scatter_kernel<<<sblocks, 256>>>(
            u2i_vals + (size_t)b * EE, u2i_rows + (size_t)b * EE,
            u2i_cols + (size_t)b * EE, zi,
            uscr + (size_t)b * NU * DD, EE);
        scatter_kernel<<<sblocks, 256>>>(
            i2u_vals + (size_t)b * EE, i2u_rows + (size_t)b * EE,
            i2u_cols + (size_t)b * EE, zu,
            iscr + (size_t)b * NI * DD, EE);
    }

    // Elementwise epilogue: sigmoid + behavior-mean sigmoid
    epilogue<<<NU * 16 / 256, 256>>>(uscr, out_ues, out_ue, NU);
    epilogue<<<NI * 16 / 256, 256>>>(iscr, out_ies, out_ie, NI);
}

// round 3
// speedup vs baseline: 1.0277x; 1.0277x over previous
#include <cuda_runtime.h>
#include <cstdint>
#include <cstddef>

#define NU 100000
#define NI 200000
#define BB 3
#define EE 1000000
#define DD 64

// Scratch accumulators (device globals: allocation-free per harness rules)
__device__ float g_uscr[(size_t)BB * NU * DD];   // 76.8 MB
__device__ float g_iscr[(size_t)BB * NI * DD];   // 153.6 MB

// ---------------------------------------------------------------------------
// Scatter: COO spmm  out[row] += val * dense[col]  (red.global.add.v4.f32)
// Identical to the R1 kernel (measured 46.9us each, L2-roofline).
// ---------------------------------------------------------------------------
__global__ void __launch_bounds__(256) scatter_kernel(
    const float* __restrict__ vals,
    const int*   __restrict__ rows,
    const int*   __restrict__ cols,
    const float* __restrict__ dense,
    float*       __restrict__ out,
    int nE)
{
    int warp = (blockIdx.x * blockDim.x + threadIdx.x) >> 5;
    int lane = threadIdx.x & 31;
    int e = warp * 32 + lane;

    float v = 0.0f; int r = 0, c = 0;
    if (e < nE) { v = vals[e]; r = rows[e]; c = cols[e]; }   // tail: v=0 -> adds 0

    int half = lane >> 4;
    int l4   = lane & 15;

    #pragma unroll
    for (int i = 0; i < 16; i++) {
        int src = 2 * i + half;
        float vv = __shfl_sync(0xffffffffu, v, src);
        int   rr = __shfl_sync(0xffffffffu, r, src);
        int   cc = __shfl_sync(0xffffffffu, c, src);

        const float4* dp = reinterpret_cast<const float4*>(dense + (size_t)cc * DD) + l4;
        float4 d = __ldg(dp);
        float4 p;
        p.x = vv * d.x; p.y = vv * d.y; p.z = vv * d.z; p.w = vv * d.w;

        float* op = out + (size_t)rr * DD + (size_t)l4 * 4;
        asm volatile("red.global.add.v4.f32 [%0], {%1,%2,%3,%4};"
                     :: "l"(op), "f"(p.x), "f"(p.y), "f"(p.z), "f"(p.w)
                     : "memory");
    }
}

// ---------------------------------------------------------------------------
// GEMM + sigmoid + in-tile mean, packed f32x2 version.
// Block tile: 32 rows x 3 behaviors x 64 cols. 256 threads.
// Thread (g=t>>5, c=t&31): rows {g+8i}, cols {c, c+32}, all 3 behaviors.
// k processed in pairs via fma.rn.f32x2:
//   x-pair  : broadcast LDS.64 from sX  (k, k+1 adjacent -> free packing)
//   w-pair  : LDS.64 from sW2 pre-paired at tile load
//   acc     : (even-k partial, odd-k partial), reduced in epilogue
// ---------------------------------------------------------------------------
__device__ __forceinline__ float sigmoidf_(float x) {
    return 1.0f / (1.0f + __expf(-x));
}

#define FMA_F32X2(d, a, b) \
    asm("fma.rn.f32x2 %0, %1, %2, %0;" : "+l"(d) : "l"(a), "l"(b))

__global__ void __launch_bounds__(256) gemm_sig(
    const float* __restrict__ scr,      // [3, N, 64]
    const float* __restrict__ W,        // [64, 64] row-major (k, col)
    float*       __restrict__ out_per,  // [3, N, 64]
    float*       __restrict__ out_mean, // [N, 64]
    int N)
{
    __shared__ float4 sX[3 * 32 * 16];  // [(b*32+r)][k/4]  24 KB (plain k-major rows)
    __shared__ float2 sW2[32 * 64];     // [k2][col] = (W[2k2][col], W[2k2+1][col]) 16 KB

    int t  = threadIdx.x;
    int n0 = blockIdx.x * 32;

    // Load x tile (96 rows x 64 floats) as float4
    const float4* scr4 = reinterpret_cast<const float4*>(scr);
    #pragma unroll
    for (int i = 0; i < 6; i++) {
        int u  = t + i * 256;          // 0..1535
        int rb = u >> 4;               // 0..95
        int kq = u & 15;
        int b  = rb >> 5;
        int r  = rb & 31;
        sX[u] = scr4[((size_t)b * N + n0 + r) * 16 + kq];
    }
    // Load W pre-paired along k: sW2[k2*64 + col] = (W[2k2][col], W[2k2+1][col])
    #pragma unroll
    for (int i = 0; i < 8; i++) {
        int j  = t + i * 256;          // 0..2047
        int k2 = j >> 6;
        int cc = j & 63;
        sW2[j] = make_float2(W[(2 * k2) * 64 + cc], W[(2 * k2 + 1) * 64 + cc]);
    }
    __syncthreads();

    int c = t & 31;
    int g = t >> 5;

    const unsigned long long* sXu = reinterpret_cast<const unsigned long long*>(sX);
    const unsigned long long* sWu = reinterpret_cast<const unsigned long long*>(sW2);

    unsigned long long acc[3][4][2];
    #pragma unroll
    for (int b = 0; b < 3; b++)
        #pragma unroll
        for (int i = 0; i < 4; i++) { acc[b][i][0] = 0ULL; acc[b][i][1] = 0ULL; }

    #pragma unroll 4
    for (int k2 = 0; k2 < 32; k2++) {
        unsigned long long w0 = sWu[k2 * 64 + c];        // (W[2k2][c],   W[2k2+1][c])
        unsigned long long w1 = sWu[k2 * 64 + c + 32];   // (W[2k2][c+32],W[2k2+1][c+32])
        #pragma unroll
        for (int b = 0; b < 3; b++)
            #pragma unroll
            for (int i = 0; i < 4; i++) {
                // broadcast (x_{2k2}, x_{2k2+1}) of row (b*32 + g + 8i)
                unsigned long long x2 = sXu[(b * 32 + g + 8 * i) * 32 + k2];
                FMA_F32X2(acc[b][i][0], x2, w0);
                FMA_F32X2(acc[b][i][1], x2, w1);
            }
    }

    // Epilogue: reduce (even,odd) partials, sigmoid per behavior + mean sigmoid
    #pragma unroll
    for (int i = 0; i < 4; i++) {
        int row = n0 + g + 8 * i;
        #pragma unroll
        for (int c2 = 0; c2 < 2; c2++) {
            int col = c + 32 * c2;
            float m = 0.0f;
            #pragma unroll
            for (int b = 0; b < 3; b++) {
                float lo, hi;
                asm("mov.b64 {%0, %1}, %2;" : "=f"(lo), "=f"(hi) : "l"(acc[b][i][c2]));
                float y = lo + hi;
                m += y;
                out_per[((size_t)b * N + row) * 64 + col] = sigmoidf_(y);
            }
            out_mean[(size_t)row * 64 + col] = sigmoidf_(m * (1.0f / 3.0f));
        }
    }
}

// ---------------------------------------------------------------------------
// Launch (R1 ordering: memset -> 6 scatters -> 2 gemms)
// ---------------------------------------------------------------------------
extern "C" void kernel_launch(void* const* d_in, const int* in_sizes, int n_in,
                              void* d_out, int out_size)
{
    const float* user_emb = (const float*)d_in[0];
    const float* item_emb = (const float*)d_in[1];
    const float* u2i_vals = (const float*)d_in[2];
    const int*   u2i_rows = (const int*)  d_in[3];
    const int*   u2i_cols = (const int*)  d_in[4];
    const float* i2u_vals = (const float*)d_in[5];
    const int*   i2u_rows = (const int*)  d_in[6];
    const int*   i2u_cols = (const int*)  d_in[7];
    const float* u_w      = (const float*)d_in[8];
    const float* i_w      = (const float*)d_in[9];

    float* out     = (float*)d_out;
    float* out_ue  = out;                                                 // [NU,64]
    float* out_ie  = out + (size_t)NU * DD;                               // [NI,64]
    float* out_ues = out + (size_t)(NU + NI) * DD;                        // [3,NU,64]
    float* out_ies = out + (size_t)(NU + NI) * DD + (size_t)BB * NU * DD; // [3,NI,64]

    void* p;
    cudaGetSymbolAddress(&p, g_uscr); float* uscr = (float*)p;
    cudaGetSymbolAddress(&p, g_iscr); float* iscr = (float*)p;

    cudaMemsetAsync(uscr, 0, sizeof(g_uscr), 0);
    cudaMemsetAsync(iscr, 0, sizeof(g_iscr), 0);

    int sblocks = (EE + 255) / 256;
    for (int b = 0; b < BB; b++) {
        scatter_kernel<<<sblocks, 256>>>(
            u2i_vals + (size_t)b * EE, u2i_rows + (size_t)b * EE,
            u2i_cols + (size_t)b * EE, item_emb,
            uscr + (size_t)b * NU * DD, EE);
        scatter_kernel<<<sblocks, 256>>>(
            i2u_vals + (size_t)b * EE, i2u_rows + (size_t)b * EE,
            i2u_cols + (size_t)b * EE, user_emb,
            iscr + (size_t)b * NI * DD, EE);
    }

    gemm_sig<<<NU / 32, 256>>>(uscr, u_w, out_ues, out_ue, NU);
    gemm_sig<<<NI / 32, 256>>>(iscr, i_w, out_ies, out_ie, NI);
}

// round 4
// speedup vs baseline: 1.1507x; 1.1197x over previous
#include <cuda_runtime.h>
#include <cstdint>
#include <cstddef>

#define NU 100000
#define NI 200000
#define BB 3
#define EE 1000000
#define DD 64

// Scratch accumulators (device globals: allocation-free per harness rules)
__device__ float g_uscr[(size_t)BB * NU * DD];   // 76.8 MB
__device__ float g_iscr[(size_t)BB * NI * DD];   // 153.6 MB

// ---------------------------------------------------------------------------
// Scatter: COO spmm  out[row] += val * dense[col]  (red.global.add.v4.f32)
// R1 kernel, measured 46.9us each (L2-crossbar roofline).
// ---------------------------------------------------------------------------
__global__ void __launch_bounds__(256) scatter_kernel(
    const float* __restrict__ vals,
    const int*   __restrict__ rows,
    const int*   __restrict__ cols,
    const float* __restrict__ dense,
    float*       __restrict__ out,
    int nE)
{
    int warp = (blockIdx.x * blockDim.x + threadIdx.x) >> 5;
    int lane = threadIdx.x & 31;
    int e = warp * 32 + lane;

    float v = 0.0f; int r = 0, c = 0;
    if (e < nE) { v = vals[e]; r = rows[e]; c = cols[e]; }   // tail: v=0 -> adds 0

    int half = lane >> 4;
    int l4   = lane & 15;

    #pragma unroll
    for (int i = 0; i < 16; i++) {
        int src = 2 * i + half;
        float vv = __shfl_sync(0xffffffffu, v, src);
        int   rr = __shfl_sync(0xffffffffu, r, src);
        int   cc = __shfl_sync(0xffffffffu, c, src);

        const float4* dp = reinterpret_cast<const float4*>(dense + (size_t)cc * DD) + l4;
        float4 d = __ldg(dp);
        float4 p;
        p.x = vv * d.x; p.y = vv * d.y; p.z = vv * d.z; p.w = vv * d.w;

        float* op = out + (size_t)rr * DD + (size_t)l4 * 4;
        asm volatile("red.global.add.v4.f32 [%0], {%1,%2,%3,%4};"
                     :: "l"(op), "f"(p.x), "f"(p.y), "f"(p.z), "f"(p.w)
                     : "memory");
    }
}

// ---------------------------------------------------------------------------
// GEMM + sigmoid + in-tile mean (R1 scalar version, ~90% of FFMA issue peak).
// Block tile: 32 rows x 3 behaviors x 64 cols. 256 threads.
// ---------------------------------------------------------------------------
__device__ __forceinline__ float sigmoidf_(float x) {
    return 1.0f / (1.0f + __expf(-x));
}

#define F4_GET(v, kk) ((kk) == 0 ? (v).x : ((kk) == 1 ? (v).y : ((kk) == 2 ? (v).z : (v).w)))

__global__ void __launch_bounds__(256) gemm_sig(
    const float* __restrict__ scr,      // [3, N, 64]
    const float* __restrict__ W,        // [64, 64] row-major (k, col)
    float*       __restrict__ out_per,  // [3, N, 64]
    float*       __restrict__ out_mean, // [N, 64]
    int N)
{
    __shared__ float4 sX[3 * 32 * 16];  // 24 KB
    __shared__ float  sW[64 * 64];      // 16 KB

    int t  = threadIdx.x;
    int n0 = blockIdx.x * 32;

    const float4* scr4 = reinterpret_cast<const float4*>(scr);
    #pragma unroll
    for (int i = 0; i < 6; i++) {
        int u  = t + i * 256;
        int rb = u >> 4;
        int kq = u & 15;
        int b  = rb >> 5;
        int r  = rb & 31;
        sX[u] = scr4[((size_t)b * N + n0 + r) * 16 + kq];
    }
    const float4* W4  = reinterpret_cast<const float4*>(W);
    float4*       sW4 = reinterpret_cast<float4*>(sW);
    #pragma unroll
    for (int i = 0; i < 4; i++) sW4[t + i * 256] = W4[t + i * 256];
    __syncthreads();

    int c = t & 31;
    int g = t >> 5;

    float acc[3][4][2];
    #pragma unroll
    for (int b = 0; b < 3; b++)
        #pragma unroll
        for (int i = 0; i < 4; i++) { acc[b][i][0] = 0.0f; acc[b][i][1] = 0.0f; }

    for (int k4 = 0; k4 < 16; k4++) {
        float4 xv[3][4];
        #pragma unroll
        for (int b = 0; b < 3; b++)
            #pragma unroll
            for (int i = 0; i < 4; i++)
                xv[b][i] = sX[(b * 32 + g + 8 * i) * 16 + k4];

        #pragma unroll
        for (int kk = 0; kk < 4; kk++) {
            int k = k4 * 4 + kk;
            float w0 = sW[k * 64 + c];
            float w1 = sW[k * 64 + c + 32];
            #pragma unroll
            for (int b = 0; b < 3; b++)
                #pragma unroll
                for (int i = 0; i < 4; i++) {
                    float xk = F4_GET(xv[b][i], kk);
                    acc[b][i][0] = fmaf(xk, w0, acc[b][i][0]);
                    acc[b][i][1] = fmaf(xk, w1, acc[b][i][1]);
                }
        }
    }

    #pragma unroll
    for (int i = 0; i < 4; i++) {
        int row = n0 + g + 8 * i;
        #pragma unroll
        for (int c2 = 0; c2 < 2; c2++) {
            int col = c + 32 * c2;
            float m = 0.0f;
            #pragma unroll
            for (int b = 0; b < 3; b++) {
                float y = acc[b][i][c2];
                m += y;
                out_per[((size_t)b * N + row) * 64 + col] = sigmoidf_(y);
            }
            out_mean[(size_t)row * 64 + col] = sigmoidf_(m * (1.0f / 3.0f));
        }
    }
}

// ---------------------------------------------------------------------------
// Lazy stream/event creation (first call = correctness run, outside capture;
// the captured graph topology is identical on every capture).
// ---------------------------------------------------------------------------
static cudaStream_t side_stream() {
    static cudaStream_t s = nullptr;
    if (!s) cudaStreamCreateWithFlags(&s, cudaStreamNonBlocking);
    return s;
}
static cudaEvent_t ev(int i) {
    static cudaEvent_t e[4] = {nullptr, nullptr, nullptr, nullptr};
    if (!e[i]) cudaEventCreateWithFlags(&e[i], cudaEventDisableTiming);
    return e[i];
}

// ---------------------------------------------------------------------------
// Launch: fork/join DAG.
//   stream0: memset_i -> i2u x3 -> u2i x3 (waits memset_u) -> gemm_u -> join
//   s1:      memset_u            -> gemm_i (waits i2u x3)  ----------^
// gemm_i (153us, FMA-bound) hides under the u2i scatters (L2-bound).
// ---------------------------------------------------------------------------
extern "C" void kernel_launch(void* const* d_in, const int* in_sizes, int n_in,
                              void* d_out, int out_size)
{
    const float* user_emb = (const float*)d_in[0];
    const float* item_emb = (const float*)d_in[1];
    const float* u2i_vals = (const float*)d_in[2];
    const int*   u2i_rows = (const int*)  d_in[3];
    const int*   u2i_cols = (const int*)  d_in[4];
    const float* i2u_vals = (const float*)d_in[5];
    const int*   i2u_rows = (const int*)  d_in[6];
    const int*   i2u_cols = (const int*)  d_in[7];
    const float* u_w      = (const float*)d_in[8];
    const float* i_w      = (const float*)d_in[9];

    float* out     = (float*)d_out;
    float* out_ue  = out;                                                 // [NU,64]
    float* out_ie  = out + (size_t)NU * DD;                               // [NI,64]
    float* out_ues = out + (size_t)(NU + NI) * DD;                        // [3,NU,64]
    float* out_ies = out + (size_t)(NU + NI) * DD + (size_t)BB * NU * DD; // [3,NI,64]

    void* p;
    cudaGetSymbolAddress(&p, g_uscr); float* uscr = (float*)p;
    cudaGetSymbolAddress(&p, g_iscr); float* iscr = (float*)p;

    cudaStream_t s1 = side_stream();
    cudaEvent_t e_fork = ev(0), e_mu = ev(1), e_i2u = ev(2), e_join = ev(3);

    // ---- fork at the very start (empty dependency set for s1) ----
    cudaEventRecord(e_fork, 0);
    cudaStreamWaitEvent(s1, e_fork, 0);

    // s1: zero user scratch (parallel with memset_i)
    cudaMemsetAsync(uscr, 0, sizeof(g_uscr), s1);
    cudaEventRecord(e_mu, s1);

    // stream0: zero item scratch, then the 3 i2u scatters
    cudaMemsetAsync(iscr, 0, sizeof(g_iscr), 0);

    int sblocks = (EE + 255) / 256;
    for (int b = 0; b < BB; b++) {
        scatter_kernel<<<sblocks, 256>>>(
            i2u_vals + (size_t)b * EE, i2u_rows + (size_t)b * EE,
            i2u_cols + (size_t)b * EE, user_emb,
            iscr + (size_t)b * NI * DD, EE);
    }
    cudaEventRecord(e_i2u, 0);

    // s1: big GEMM on item scratch, concurrent with u2i scatters below
    cudaStreamWaitEvent(s1, e_i2u, 0);
    gemm_sig<<<NI / 32, 256, 0, s1>>>(iscr, i_w, out_ies, out_ie, NI);
    cudaEventRecord(e_join, s1);

    // stream0: u2i scatters (need memset_u from s1)
    cudaStreamWaitEvent(0, e_mu, 0);
    for (int b = 0; b < BB; b++) {
        scatter_kernel<<<sblocks, 256>>>(
            u2i_vals + (size_t)b * EE, u2i_rows + (size_t)b * EE,
            u2i_cols + (size_t)b * EE, item_emb,
            uscr + (size_t)b * NU * DD, EE);
    }
    gemm_sig<<<NU / 32, 256>>>(uscr, u_w, out_ues, out_ue, NU);

    // join s1 back into the origin stream
    cudaStreamWaitEvent(0, e_join, 0);
}